// round 9
// baseline (speedup 1.0000x reference)
#include <cuda_runtime.h>
#include <cstdint>

// InstantNGP: hash-grid encode + MLP 32->64->64->3 via warp-level tf32 mma.sync.
// Round-9: 2x2 hybrid. CTA = 2 groups x 2 warps. Group owns 32 points/iter
// (M=32); within group, warp w owns hidden cols [32w,32w+32) (N-split=2).
// B fragments packed as uint4 (2 k-steps/load). Named barriers per group.

namespace {

constexpr int S_DIM   = 1024;
constexpr int NPTS    = S_DIM * S_DIM;
constexpr int TBL     = 1 << 19;

constexpr int THREADS = 128;
constexpr int MT      = 64;                  // points per CTA iteration (2 groups x 32)
constexpr int ITERS   = 8;
constexpr int GRID    = NPTS / (MT * ITERS); // 2048

constexpr int GRP_STRIDE = 32 * 32 + 32 * 64;          // enc + h0 per group (uints)
constexpr int DYN_SMEM   = 2 * GRP_STRIDE * 4;         // 24 KB

__device__ __forceinline__ uint32_t tf32_rna(float x) {
    uint32_t r;
    asm("cvt.rna.tf32.f32 %0, %1;" : "=r"(r) : "f"(x));
    return r;
}

// swizzled addressing (xor bits 2..4 with row low bits)
__device__ __forceinline__ int eix(int row, int col) {   // enc: stride 32
    return row * 32 + (col ^ ((row & 7) << 2));
}
__device__ __forceinline__ int hix(int row, int col) {   // h0: stride 64
    return row * 64 + (col ^ ((row & 7) << 2));
}

// enc column kp -> original W0 row (level-parity packed layout)
__device__ __forceinline__ int orig_k(int kp) {
    const int h = kp >> 4, rem = kp & 15;
    return 4 * (rem >> 1) + 2 * h + (rem & 1);
}

__device__ __forceinline__ void mma8(float* d,
                                     uint32_t a0, uint32_t a1, uint32_t a2, uint32_t a3,
                                     uint32_t b0, uint32_t b1) {
    asm volatile(
        "mma.sync.aligned.m16n8k8.row.col.f32.tf32.tf32.f32 "
        "{%0,%1,%2,%3},{%4,%5,%6,%7},{%8,%9},{%0,%1,%2,%3};"
        : "+f"(d[0]), "+f"(d[1]), "+f"(d[2]), "+f"(d[3])
        : "r"(a0), "r"(a1), "r"(a2), "r"(a3), "r"(b0), "r"(b1));
}

__device__ __forceinline__ void gbar(int id) {
    asm volatile("bar.sync %0, 64;" :: "r"(id) : "memory");
}

__global__ __launch_bounds__(THREADS, 4) void ngp_mma_kernel(
    const float2* __restrict__ xy,
    const float2* __restrict__ tab,
    const float*  __restrict__ W0,     // (32, 64) [k][n]
    const float*  __restrict__ W1,     // (64, 64) [k][n]
    const float*  __restrict__ W2,     // (64, 3)
    float*        __restrict__ out)    // (3, S, S)
{
    __shared__ uint4 w0q[2 * 8 * 32];   //  8 KB  B frags layer0 (k-pairs)
    __shared__ uint4 w1q[4 * 8 * 32];   // 16 KB  B frags layer1 (k-pairs)
    __shared__ float w2s[3 * 64];       // packed [j][c]
    __shared__ float part[2][32][2][3]; // group partials
    extern __shared__ uint32_t dynscr[];

    const int tid = threadIdx.x;

    // ---- stage weights in fragment order (once per CTA) ----
    for (int i = tid; i < 2 * 8 * 32; i += THREADS) {
        const int kq = i >> 8, nt = (i >> 5) & 7, ln = i & 31;
        const int t = ln & 3, g = ln >> 2, n = nt * 8 + g;
        w0q[i] = make_uint4(tf32_rna(W0[orig_k(16 * kq + t) * 64 + n]),
                            tf32_rna(W0[orig_k(16 * kq + t + 4) * 64 + n]),
                            tf32_rna(W0[orig_k(16 * kq + 8 + t) * 64 + n]),
                            tf32_rna(W0[orig_k(16 * kq + 8 + t + 4) * 64 + n]));
    }
    for (int i = tid; i < 4 * 8 * 32; i += THREADS) {
        const int kq = i >> 8, nt = (i >> 5) & 7, ln = i & 31;
        const int t = ln & 3, g = ln >> 2, n = nt * 8 + g;
        w1q[i] = make_uint4(tf32_rna(W1[(16 * kq + t) * 64 + n]),
                            tf32_rna(W1[(16 * kq + t + 4) * 64 + n]),
                            tf32_rna(W1[(16 * kq + 8 + t) * 64 + n]),
                            tf32_rna(W1[(16 * kq + 8 + t + 4) * 64 + n]));
    }
    for (int i = tid; i < 3 * 64; i += THREADS) {
        const int j = i >> 6, c = i & 63;
        w2s[i] = W2[c * 3 + j];
    }
    __syncthreads();

    const int wid  = tid >> 5;
    const int lane = tid & 31;
    const int t    = lane & 3;
    const int g    = lane >> 2;
    const int grp  = wid >> 1;          // group 0/1
    const int wln  = wid & 1;           // N-half within group
    const int lt   = tid & 63;          // thread within group
    const int h    = lt & 1;            // level parity for encode
    const int pt   = lt >> 1;           // point row (0..31) for encode
    const int bid  = grp + 1;           // named barrier id

    uint32_t* enc = dynscr + grp * GRP_STRIDE;
    uint32_t* h0  = enc + 32 * 32;

    // floor(16 * 1.5^l): even levels / odd levels
    const int res_e[8] = {16, 36, 81, 182, 410, 922, 2075, 4670};
    const int res_o[8] = {24, 54, 121, 273, 615, 1383, 3113, 7006};

    for (int it = 0; it < ITERS; it++) {
        const int base = (blockIdx.x * ITERS + it) * MT + grp * 32;

        // ---- encode: 32 points/group, 2 threads/point (even/odd levels) ----
        {
            const float2 p = __ldg(&xy[base + pt]);
            const float c0 = p.x, c1 = p.y;
#pragma unroll
            for (int q = 0; q < 4; q++) {
                float fv[4];
#pragma unroll
                for (int s = 0; s < 2; s++) {
                    const int lp    = 2 * q + s;
                    const int res   = h ? res_o[lp] : res_e[lp];
                    const int level = 2 * lp + h;
                    const bool dense = (lp < 5);

                    const float fres = (float)res;
                    const float px = c0 * fres;
                    const float py = c1 * fres;
                    const float fx = floorf(px);
                    const float fy = floorf(py);
                    const float wx = px - fx;
                    const float wy = py - fy;
                    const int ix = (int)fx;
                    const int iy = (int)fy;

                    int i00, i01, i10, i11;
                    if (dense) {
                        const int r1 = res + 1;
                        i00 = ix + iy * r1;
                        i01 = i00 + r1;
                        i10 = i00 + 1;
                        i11 = i01 + 1;
                    } else {
                        const uint32_t P = 2654435761u;
                        const uint32_t ux = (uint32_t)ix;
                        const uint32_t uy = (uint32_t)iy;
                        const uint32_t hy0 = uy * P;
                        const uint32_t hy1 = (uy + 1u) * P;
                        i00 = (int)((ux        ^ hy0) & (uint32_t)(TBL - 1));
                        i01 = (int)((ux        ^ hy1) & (uint32_t)(TBL - 1));
                        i10 = (int)(((ux + 1u) ^ hy0) & (uint32_t)(TBL - 1));
                        i11 = (int)(((ux + 1u) ^ hy1) & (uint32_t)(TBL - 1));
                    }

                    const float2* lt2 = tab + (size_t)level * TBL;
                    const float2 a00 = __ldg(lt2 + i00);
                    const float2 a01 = __ldg(lt2 + i01);
                    const float2 a10 = __ldg(lt2 + i10);
                    const float2 a11 = __ldg(lt2 + i11);

                    const float w00 = (1.0f - wx) * (1.0f - wy);
                    const float w01 = (1.0f - wx) * wy;
                    const float w10 = wx * (1.0f - wy);
                    const float w11 = wx * wy;

                    fv[2 * s]     = a00.x * w00 + a01.x * w01 + a10.x * w10 + a11.x * w11;
                    fv[2 * s + 1] = a00.y * w00 + a01.y * w01 + a10.y * w10 + a11.y * w11;
                }
                *reinterpret_cast<uint4*>(&enc[eix(pt, 16 * h + 4 * q)]) =
                    make_uint4(tf32_rna(fv[0]), tf32_rna(fv[1]),
                               tf32_rna(fv[2]), tf32_rna(fv[3]));
            }
        }
        gbar(bid);

        // ---- layer 0: warp computes cols [32*wln, 32*wln+32) for 32 rows ----
        float C[2][4][4];
#pragma unroll
        for (int m = 0; m < 2; m++)
#pragma unroll
            for (int nt = 0; nt < 4; nt++)
#pragma unroll
                for (int q = 0; q < 4; q++) C[m][nt][q] = 0.0f;

#pragma unroll
        for (int kq = 0; kq < 2; kq++) {
            uint32_t a[2][2][4];
#pragma unroll
            for (int m = 0; m < 2; m++)
#pragma unroll
                for (int ks = 0; ks < 2; ks++) {
                    const int col = 16 * kq + 8 * ks + t;
                    const int r0 = 16 * m + g, r1 = r0 + 8;
                    a[m][ks][0] = enc[eix(r0, col)];
                    a[m][ks][1] = enc[eix(r1, col)];
                    a[m][ks][2] = enc[eix(r0, col + 4)];
                    a[m][ks][3] = enc[eix(r1, col + 4)];
                }
#pragma unroll
            for (int nt = 0; nt < 4; nt++) {
                const uint4 b = w0q[(kq * 8 + 4 * wln + nt) * 32 + lane];
#pragma unroll
                for (int m = 0; m < 2; m++) {
                    mma8(C[m][nt], a[m][0][0], a[m][0][1], a[m][0][2], a[m][0][3], b.x, b.y);
                    mma8(C[m][nt], a[m][1][0], a[m][1][1], a[m][1][2], a[m][1][3], b.z, b.w);
                }
            }
        }

        // ---- relu + store h0 slice (cols 32*wln + nt*8 + 2t) ----
#pragma unroll
        for (int m = 0; m < 2; m++) {
            const int r0 = 16 * m + g, r1 = r0 + 8;
#pragma unroll
            for (int nt = 0; nt < 4; nt++) {
                const int col = 32 * wln + nt * 8 + 2 * t;
                *reinterpret_cast<uint2*>(&h0[hix(r0, col)]) =
                    make_uint2(tf32_rna(fmaxf(C[m][nt][0], 0.0f)),
                               tf32_rna(fmaxf(C[m][nt][1], 0.0f)));
                *reinterpret_cast<uint2*>(&h0[hix(r1, col)]) =
                    make_uint2(tf32_rna(fmaxf(C[m][nt][2], 0.0f)),
                               tf32_rna(fmaxf(C[m][nt][3], 0.0f)));
            }
        }
        gbar(bid);

        // ---- layer 1: (32x64)@(64x64) slice, 4 k-pairs ----
#pragma unroll
        for (int m = 0; m < 2; m++)
#pragma unroll
            for (int nt = 0; nt < 4; nt++)
#pragma unroll
                for (int q = 0; q < 4; q++) C[m][nt][q] = 0.0f;

#pragma unroll
        for (int kq = 0; kq < 4; kq++) {
            uint32_t a[2][2][4];
#pragma unroll
            for (int m = 0; m < 2; m++)
#pragma unroll
                for (int ks = 0; ks < 2; ks++) {
                    const int col = 16 * kq + 8 * ks + t;
                    const int r0 = 16 * m + g, r1 = r0 + 8;
                    a[m][ks][0] = h0[hix(r0, col)];
                    a[m][ks][1] = h0[hix(r1, col)];
                    a[m][ks][2] = h0[hix(r0, col + 4)];
                    a[m][ks][3] = h0[hix(r1, col + 4)];
                }
#pragma unroll
            for (int nt = 0; nt < 4; nt++) {
                const uint4 b = w1q[(kq * 8 + 4 * wln + nt) * 32 + lane];
#pragma unroll
                for (int m = 0; m < 2; m++) {
                    mma8(C[m][nt], a[m][0][0], a[m][0][1], a[m][0][2], a[m][0][3], b.x, b.y);
                    mma8(C[m][nt], a[m][1][0], a[m][1][1], a[m][1][2], a[m][1][3], b.z, b.w);
                }
            }
        }

        // ---- epilogue: relu + partial (32-col) dot with W2 ----
        float pa[2][2][3];
#pragma unroll
        for (int m = 0; m < 2; m++)
#pragma unroll
            for (int r = 0; r < 2; r++)
#pragma unroll
                for (int j = 0; j < 3; j++) pa[m][r][j] = 0.0f;

#pragma unroll
        for (int nt = 0; nt < 4; nt++) {
            const int cA = 32 * wln + nt * 8 + 2 * t;
            float2 w[3];
#pragma unroll
            for (int j = 0; j < 3; j++)
                w[j] = *reinterpret_cast<const float2*>(&w2s[j * 64 + cA]);
#pragma unroll
            for (int m = 0; m < 2; m++) {
                const float vA0 = fmaxf(C[m][nt][0], 0.0f);
                const float vB0 = fmaxf(C[m][nt][1], 0.0f);
                const float vA1 = fmaxf(C[m][nt][2], 0.0f);
                const float vB1 = fmaxf(C[m][nt][3], 0.0f);
#pragma unroll
                for (int j = 0; j < 3; j++) {
                    pa[m][0][j] += vA0 * w[j].x + vB0 * w[j].y;
                    pa[m][1][j] += vA1 * w[j].x + vB1 * w[j].y;
                }
            }
        }
#pragma unroll
        for (int m = 0; m < 2; m++)
#pragma unroll
            for (int r = 0; r < 2; r++)
#pragma unroll
                for (int j = 0; j < 3; j++) {
                    float v = pa[m][r][j];
                    v += __shfl_xor_sync(0xffffffffu, v, 1);
                    v += __shfl_xor_sync(0xffffffffu, v, 2);
                    pa[m][r][j] = v;
                }
        if (t == 0) {
#pragma unroll
            for (int m = 0; m < 2; m++)
#pragma unroll
                for (int r = 0; r < 2; r++) {
                    const int row = 16 * m + 8 * r + g;
#pragma unroll
                    for (int j = 0; j < 3; j++)
                        part[grp][row][wln][j] = pa[m][r][j];
                }
        }
        gbar(bid);

        // ---- combine partials + store (coalesced per j-plane) ----
        for (int i = lt; i < 3 * 32; i += 64) {
            const int j = i >> 5, p = i & 31;
            out[j * NPTS + base + p] = part[grp][p][0][j] + part[grp][p][1][j];
        }
    }
}

}  // namespace

extern "C" void kernel_launch(void* const* d_in, const int* in_sizes, int n_in,
                              void* d_out, int out_size) {
    (void)in_sizes; (void)n_in; (void)out_size;
    const float2* xy  = (const float2*)d_in[0];
    const float2* tab = (const float2*)d_in[1];
    const float*  W0  = (const float*)d_in[2];
    const float*  W1  = (const float*)d_in[3];
    const float*  W2  = (const float*)d_in[4];
    float* out = (float*)d_out;

    cudaFuncSetAttribute(ngp_mma_kernel,
                         cudaFuncAttributeMaxDynamicSharedMemorySize, DYN_SMEM);
    ngp_mma_kernel<<<GRID, THREADS, DYN_SMEM>>>(xy, tab, W0, W1, W2, out);
}

// round 10
// speedup vs baseline: 1.8441x; 1.8441x over previous
#include <cuda_runtime.h>
#include <cstdint>

// InstantNGP: hash-grid encode + MLP 32->64->64->3 via warp-level tf32 mma.sync.
// Round-10 = R4 skeleton + fragment passthrough: W1 rows permuted per 8-group
// (pos t <- unit 2t, pos t+4 <- unit 2t+1) so layer0 C fragments feed layer1
// directly as A fragments (a0,a1,a2,a3) = (C0,C2,C1,C3). No h0 SMEM roundtrip.

namespace {

constexpr int S_DIM   = 1024;
constexpr int NPTS    = S_DIM * S_DIM;
constexpr int TBL     = 1 << 19;

constexpr int WARPS   = 4;
constexpr int THREADS = WARPS * 32;
constexpr int TILE    = 16;               // points per warp-tile
constexpr int TPW     = 8;                // tiles per warp
constexpr int PPW     = TILE * TPW;       // 128 points per warp
constexpr int GRID    = NPTS / (PPW * WARPS);   // 2048
constexpr int BSTRIDE = 36;               // floats per scratch row (enc only)

__device__ __forceinline__ uint32_t tf32_rna(float x) {
    uint32_t r;
    asm("cvt.rna.tf32.f32 %0, %1;" : "=r"(r) : "f"(x));
    return r;
}

__device__ __forceinline__ void mma8(float* d,
                                     uint32_t a0, uint32_t a1, uint32_t a2, uint32_t a3,
                                     uint32_t b0, uint32_t b1) {
    asm volatile(
        "mma.sync.aligned.m16n8k8.row.col.f32.tf32.tf32.f32 "
        "{%0,%1,%2,%3},{%4,%5,%6,%7},{%8,%9},{%0,%1,%2,%3};"
        : "+f"(d[0]), "+f"(d[1]), "+f"(d[2]), "+f"(d[3])
        : "r"(a0), "r"(a1), "r"(a2), "r"(a3), "r"(b0), "r"(b1));
}

__global__ __launch_bounds__(THREADS, 4) void ngp_mma_kernel(
    const float2* __restrict__ xy,
    const float2* __restrict__ tab,
    const float*  __restrict__ W0,     // (32, 64) [k][n]
    const float*  __restrict__ W1,     // (64, 64) [k][n]
    const float*  __restrict__ W2,     // (64, 3)
    float*        __restrict__ out)    // (3, S, S)
{
    __shared__ uint2    w0f[4 * 8 * 32];             //  8 KB  B frags layer0
    __shared__ uint2    w1f[8 * 8 * 32];             // 16 KB  B frags layer1 (rows permuted)
    __shared__ float    w2s[3 * 64];                 // packed [j][c]
    __shared__ uint32_t scratch[WARPS][TILE * BSTRIDE];  // 9.2 KB (enc only)

    const int tid = threadIdx.x;

    // ---- stage weights in fragment order (once per CTA) ----
    for (int i = tid; i < 4 * 8 * 32; i += THREADS) {
        const int k = i >> 8, nt = (i >> 5) & 7, ln = i & 31;
        const int t = ln & 3, g = ln >> 2;
        w0f[i] = make_uint2(tf32_rna(W0[(8 * k + t) * 64 + nt * 8 + g]),
                            tf32_rna(W0[(8 * k + t + 4) * 64 + nt * 8 + g]));
    }
    // W1: within each 8-row k-group, stage row (8k + 2t) at pos t and
    // row (8k + 2t + 1) at pos t+4 so layer0 C fragments pass through as A.
    for (int i = tid; i < 8 * 8 * 32; i += THREADS) {
        const int k = i >> 8, nt = (i >> 5) & 7, ln = i & 31;
        const int t = ln & 3, g = ln >> 2;
        w1f[i] = make_uint2(tf32_rna(W1[(8 * k + 2 * t) * 64 + nt * 8 + g]),
                            tf32_rna(W1[(8 * k + 2 * t + 1) * 64 + nt * 8 + g]));
    }
    for (int i = tid; i < 3 * 64; i += THREADS) {
        const int j = i >> 6, c = i & 63;
        w2s[i] = W2[c * 3 + j];
    }
    __syncthreads();

    const int wid  = tid >> 5;
    const int lane = tid & 31;
    const int t    = lane & 3;          // threadIDInGroup
    const int g    = lane >> 2;         // groupID (row within 8)
    const int h    = lane >> 4;         // level parity for encode
    const int pl   = lane & 15;         // point within tile for encode
    uint32_t* buf  = scratch[wid];
    const int wg   = blockIdx.x * WARPS + wid;

    // floor(16 * 1.5^l): even levels / odd levels
    const int res_e[8] = {16, 36, 81, 182, 410, 922, 2075, 4670};
    const int res_o[8] = {24, 54, 121, 273, 615, 1383, 3113, 7006};

    for (int tile = 0; tile < TPW; tile++) {
        const int tb = wg * PPW + tile * TILE;
        __syncwarp();

        // ---- encode: point pl, levels 2*lp + h ----
        const float2 p = __ldg(&xy[tb + pl]);
        const float c0 = p.x, c1 = p.y;
#pragma unroll
        for (int lp = 0; lp < 8; lp++) {
            const int res   = h ? res_o[lp] : res_e[lp];
            const int level = 2 * lp + h;
            const bool dense = (lp < 5);   // levels 0..9 dense, 10..15 hashed

            const float fres = (float)res;
            const float px = c0 * fres;
            const float py = c1 * fres;
            const float fx = floorf(px);
            const float fy = floorf(py);
            const float wx = px - fx;
            const float wy = py - fy;
            const int ix = (int)fx;
            const int iy = (int)fy;

            int i00, i01, i10, i11;
            if (dense) {
                const int r1 = res + 1;
                i00 = ix + iy * r1;
                i01 = i00 + r1;
                i10 = i00 + 1;
                i11 = i01 + 1;
            } else {
                const uint32_t P = 2654435761u;
                const uint32_t ux = (uint32_t)ix;
                const uint32_t uy = (uint32_t)iy;
                const uint32_t hy0 = uy * P;
                const uint32_t hy1 = (uy + 1u) * P;
                i00 = (int)((ux        ^ hy0) & (uint32_t)(TBL - 1));
                i01 = (int)((ux        ^ hy1) & (uint32_t)(TBL - 1));
                i10 = (int)(((ux + 1u) ^ hy0) & (uint32_t)(TBL - 1));
                i11 = (int)(((ux + 1u) ^ hy1) & (uint32_t)(TBL - 1));
            }

            const float2* lt = tab + (size_t)level * TBL;
            const float2 a00 = __ldg(lt + i00);
            const float2 a01 = __ldg(lt + i01);
            const float2 a10 = __ldg(lt + i10);
            const float2 a11 = __ldg(lt + i11);

            const float w00 = (1.0f - wx) * (1.0f - wy);
            const float w01 = (1.0f - wx) * wy;
            const float w10 = wx * (1.0f - wy);
            const float w11 = wx * wy;

            const float f0 = a00.x * w00 + a01.x * w01 + a10.x * w10 + a11.x * w11;
            const float f1 = a00.y * w00 + a01.y * w01 + a10.y * w10 + a11.y * w11;

            *reinterpret_cast<uint2*>(&buf[pl * BSTRIDE + 4 * lp + 2 * h]) =
                make_uint2(tf32_rna(f0), tf32_rna(f1));
        }
        __syncwarp();

        // ---- layer 0: (16x32) @ (32x64), m16n8k8, 4 K-steps x 8 N-tiles ----
        float C[8][4];
#pragma unroll
        for (int nt = 0; nt < 8; nt++)
#pragma unroll
            for (int j = 0; j < 4; j++) C[nt][j] = 0.0f;

#pragma unroll
        for (int k = 0; k < 4; k++) {
            const uint32_t a0 = buf[g * BSTRIDE + 8 * k + t];
            const uint32_t a1 = buf[(g + 8) * BSTRIDE + 8 * k + t];
            const uint32_t a2 = buf[g * BSTRIDE + 8 * k + t + 4];
            const uint32_t a3 = buf[(g + 8) * BSTRIDE + 8 * k + t + 4];
#pragma unroll
            for (int nt = 0; nt < 8; nt++) {
                const uint2 b = w0f[(k * 8 + nt) * 32 + lane];
                mma8(C[nt], a0, a1, a2, a3, b.x, b.y);
            }
        }

        // ---- layer 1: fragment passthrough, no SMEM roundtrip ----
        // A for k-step k = relu+tf32 of C[k], permuted (C0, C2, C1, C3).
        float C1[8][4];
#pragma unroll
        for (int nt = 0; nt < 8; nt++)
#pragma unroll
            for (int j = 0; j < 4; j++) C1[nt][j] = 0.0f;

#pragma unroll
        for (int k = 0; k < 8; k++) {
            const uint32_t a0 = tf32_rna(fmaxf(C[k][0], 0.0f));
            const uint32_t a1 = tf32_rna(fmaxf(C[k][2], 0.0f));
            const uint32_t a2 = tf32_rna(fmaxf(C[k][1], 0.0f));
            const uint32_t a3 = tf32_rna(fmaxf(C[k][3], 0.0f));
#pragma unroll
            for (int nt = 0; nt < 8; nt++) {
                const uint2 b = w1f[(k * 8 + nt) * 32 + lane];
                mma8(C1[nt], a0, a1, a2, a3, b.x, b.y);
            }
        }

        // ---- epilogue: relu + (64x3) from C1 frags, shfl reduce over t ----
        float acc[2][3] = {{0.f, 0.f, 0.f}, {0.f, 0.f, 0.f}};
#pragma unroll
        for (int nt = 0; nt < 8; nt++) {
            const int cA = nt * 8 + 2 * t;
            float2 w[3];
#pragma unroll
            for (int j = 0; j < 3; j++)
                w[j] = *reinterpret_cast<const float2*>(&w2s[j * 64 + cA]);
            const float vA0 = fmaxf(C1[nt][0], 0.0f);
            const float vB0 = fmaxf(C1[nt][1], 0.0f);
            const float vA1 = fmaxf(C1[nt][2], 0.0f);
            const float vB1 = fmaxf(C1[nt][3], 0.0f);
#pragma unroll
            for (int j = 0; j < 3; j++) {
                acc[0][j] += vA0 * w[j].x + vB0 * w[j].y;
                acc[1][j] += vA1 * w[j].x + vB1 * w[j].y;
            }
        }
#pragma unroll
        for (int r = 0; r < 2; r++)
#pragma unroll
            for (int j = 0; j < 3; j++) {
                float v = acc[r][j];
                v += __shfl_xor_sync(0xffffffffu, v, 1);
                v += __shfl_xor_sync(0xffffffffu, v, 2);
                acc[r][j] = v;
            }
        if (t == 0) {
#pragma unroll
            for (int r = 0; r < 2; r++) {
                const int pid = tb + g + 8 * r;
#pragma unroll
                for (int j = 0; j < 3; j++) out[j * NPTS + pid] = acc[r][j];
            }
        }
    }
}

}  // namespace

extern "C" void kernel_launch(void* const* d_in, const int* in_sizes, int n_in,
                              void* d_out, int out_size) {
    (void)in_sizes; (void)n_in; (void)out_size;
    const float2* xy  = (const float2*)d_in[0];
    const float2* tab = (const float2*)d_in[1];
    const float*  W0  = (const float*)d_in[2];
    const float*  W1  = (const float*)d_in[3];
    const float*  W2  = (const float*)d_in[4];
    float* out = (float*)d_out;

    ngp_mma_kernel<<<GRID, THREADS>>>(xy, tab, W0, W1, W2, out);
}

// round 11
// speedup vs baseline: 2.5871x; 1.4029x over previous
#include <cuda_runtime.h>
#include <cstdint>

// InstantNGP: hash-grid encode + MLP 32->64->64->3 via warp-level fp16 mma.sync
// m16n8k16 (f32 accumulate). Round-11 = R10 skeleton with:
//  - fp16 operands (same 11-bit significand as tf32 -> same error), K=16/MMA:
//    MMA count and B-fragment SMEM bytes halved.
//  - enc features scaled by 2^8 at f16 pack (bit-exact) to avoid fp16
//    subnormals; 2^-8 folded into fp32 W2 staging.
//  - layer0 C frags pass through to layer1 A frags via cvt.rn.f16x2 packs
//    (natural W1 order, no permutation, no SMEM roundtrip).
//  - enc scratch: stride-20 uint32 + xor swizzle, conflict-free loads+stores.

namespace {

constexpr int S_DIM   = 1024;
constexpr int NPTS    = S_DIM * S_DIM;
constexpr int TBL     = 1 << 19;

constexpr int WARPS   = 4;
constexpr int THREADS = WARPS * 32;
constexpr int TILE    = 16;               // points per warp-tile
constexpr int TPW     = 8;                // tiles per warp
constexpr int PPW     = TILE * TPW;       // 128 points per warp
constexpr int GRID    = NPTS / (PPW * WARPS);   // 2048
constexpr int ESTRIDE = 20;               // uint32 per enc row (swizzled, conflict-free)
constexpr float ESCALE   = 256.0f;        // 2^8: lift enc out of fp16 subnormal range
constexpr float ESCALE_I = 1.0f / 256.0f;

__device__ __forceinline__ uint32_t f16x2(float lo, float hi) {
    uint32_t r;
    asm("cvt.rn.f16x2.f32 %0, %1, %2;" : "=r"(r) : "f"(hi), "f"(lo));
    return r;
}

// enc scratch addressing: row*20 + (col ^ ((row>>3)<<1)) -> conflict-free for
// both encode stores (lanes = (h,pl)) and A-frag loads (lanes = (t,g)).
__device__ __forceinline__ int eidx(int row, int col) {
    return row * ESTRIDE + (col ^ ((row >> 3) << 1));
}

__device__ __forceinline__ void mma16(float* d,
                                      uint32_t a0, uint32_t a1, uint32_t a2, uint32_t a3,
                                      uint32_t b0, uint32_t b1) {
    asm volatile(
        "mma.sync.aligned.m16n8k16.row.col.f32.f16.f16.f32 "
        "{%0,%1,%2,%3},{%4,%5,%6,%7},{%8,%9},{%0,%1,%2,%3};"
        : "+f"(d[0]), "+f"(d[1]), "+f"(d[2]), "+f"(d[3])
        : "r"(a0), "r"(a1), "r"(a2), "r"(a3), "r"(b0), "r"(b1));
}

__global__ __launch_bounds__(THREADS, 4) void ngp_mma_kernel(
    const float2* __restrict__ xy,
    const float2* __restrict__ tab,
    const float*  __restrict__ W0,     // (32, 64) [k][n]
    const float*  __restrict__ W1,     // (64, 64) [k][n]
    const float*  __restrict__ W2,     // (64, 3)
    float*        __restrict__ out)    // (3, S, S)
{
    __shared__ uint2    w0f[2 * 8 * 32];               // 4 KB  B frags layer0 (fp16)
    __shared__ uint2    w1f[4 * 8 * 32];               // 8 KB  B frags layer1 (fp16)
    __shared__ float    w2s[3 * 64];                   // packed [j][c], pre-scaled
    __shared__ uint32_t scratch[WARPS][TILE * ESTRIDE];  // 5 KB enc (fp16x2)

    const int tid = threadIdx.x;

    // ---- stage weights in fragment order (once per CTA) ----
    // B frag (m16n8k16, col-major): b0 = k-rows (16kk+2t, +1) col n,
    //                               b1 = k-rows (16kk+2t+8, +9) col n.
    for (int i = tid; i < 2 * 8 * 32; i += THREADS) {
        const int kk = i >> 8, nt = (i >> 5) & 7, ln = i & 31;
        const int t = ln & 3, g = ln >> 2, n = nt * 8 + g;
        const int kb = 16 * kk + 2 * t;
        w0f[i] = make_uint2(f16x2(W0[kb * 64 + n],       W0[(kb + 1) * 64 + n]),
                            f16x2(W0[(kb + 8) * 64 + n], W0[(kb + 9) * 64 + n]));
    }
    for (int i = tid; i < 4 * 8 * 32; i += THREADS) {
        const int kk = i >> 8, nt = (i >> 5) & 7, ln = i & 31;
        const int t = ln & 3, g = ln >> 2, n = nt * 8 + g;
        const int kb = 16 * kk + 2 * t;
        w1f[i] = make_uint2(f16x2(W1[kb * 64 + n],       W1[(kb + 1) * 64 + n]),
                            f16x2(W1[(kb + 8) * 64 + n], W1[(kb + 9) * 64 + n]));
    }
    for (int i = tid; i < 3 * 64; i += THREADS) {
        const int j = i >> 6, c = i & 63;
        w2s[i] = W2[c * 3 + j] * ESCALE_I;   // undo enc scaling here
    }
    __syncthreads();

    const int wid  = tid >> 5;
    const int lane = tid & 31;
    const int t    = lane & 3;          // threadIDInGroup
    const int g    = lane >> 2;         // groupID (row within 8)
    const int h    = lane >> 4;         // level parity for encode
    const int pl   = lane & 15;         // point within tile for encode
    uint32_t* buf  = scratch[wid];
    const int wg   = blockIdx.x * WARPS + wid;

    // floor(16 * 1.5^l): even levels / odd levels
    const int res_e[8] = {16, 36, 81, 182, 410, 922, 2075, 4670};
    const int res_o[8] = {24, 54, 121, 273, 615, 1383, 3113, 7006};

    for (int tile = 0; tile < TPW; tile++) {
        const int tb = wg * PPW + tile * TILE;
        __syncwarp();

        // ---- encode: point pl, levels 2*lp + h; store fp16x2 (f0,f1)*2^8 ----
        const float2 p = __ldg(&xy[tb + pl]);
        const float c0 = p.x, c1 = p.y;
#pragma unroll
        for (int lp = 0; lp < 8; lp++) {
            const int res   = h ? res_o[lp] : res_e[lp];
            const int level = 2 * lp + h;
            const bool dense = (lp < 5);   // levels 0..9 dense, 10..15 hashed

            const float fres = (float)res;
            const float px = c0 * fres;
            const float py = c1 * fres;
            const float fx = floorf(px);
            const float fy = floorf(py);
            const float wx = px - fx;
            const float wy = py - fy;
            const int ix = (int)fx;
            const int iy = (int)fy;

            int i00, i01, i10, i11;
            if (dense) {
                const int r1 = res + 1;
                i00 = ix + iy * r1;
                i01 = i00 + r1;
                i10 = i00 + 1;
                i11 = i01 + 1;
            } else {
                const uint32_t P = 2654435761u;
                const uint32_t ux = (uint32_t)ix;
                const uint32_t uy = (uint32_t)iy;
                const uint32_t hy0 = uy * P;
                const uint32_t hy1 = (uy + 1u) * P;
                i00 = (int)((ux        ^ hy0) & (uint32_t)(TBL - 1));
                i01 = (int)((ux        ^ hy1) & (uint32_t)(TBL - 1));
                i10 = (int)(((ux + 1u) ^ hy0) & (uint32_t)(TBL - 1));
                i11 = (int)(((ux + 1u) ^ hy1) & (uint32_t)(TBL - 1));
            }

            const float2* lt = tab + (size_t)level * TBL;
            const float2 a00 = __ldg(lt + i00);
            const float2 a01 = __ldg(lt + i01);
            const float2 a10 = __ldg(lt + i10);
            const float2 a11 = __ldg(lt + i11);

            const float w00 = (1.0f - wx) * (1.0f - wy);
            const float w01 = (1.0f - wx) * wy;
            const float w10 = wx * (1.0f - wy);
            const float w11 = wx * wy;

            const float f0 = a00.x * w00 + a01.x * w01 + a10.x * w10 + a11.x * w11;
            const float f1 = a00.y * w00 + a01.y * w01 + a10.y * w10 + a11.y * w11;

            buf[eidx(pl, level)] = f16x2(f0 * ESCALE, f1 * ESCALE);
        }
        __syncwarp();

        // ---- layer 0: (16x32) @ (32x64), m16n8k16, 2 K-blocks x 8 N-tiles ----
        float C[8][4];
#pragma unroll
        for (int nt = 0; nt < 8; nt++)
#pragma unroll
            for (int j = 0; j < 4; j++) C[nt][j] = 0.0f;

#pragma unroll
        for (int kk = 0; kk < 2; kk++) {
            // A frag: cols 16kk+2t,+1 = level 8kk+t (both feats) etc.
            const uint32_t a0 = buf[eidx(g,     8 * kk + t)];
            const uint32_t a1 = buf[eidx(g + 8, 8 * kk + t)];
            const uint32_t a2 = buf[eidx(g,     8 * kk + t + 4)];
            const uint32_t a3 = buf[eidx(g + 8, 8 * kk + t + 4)];
#pragma unroll
            for (int nt = 0; nt < 8; nt++) {
                const uint2 b = w0f[(kk * 8 + nt) * 32 + lane];
                mma16(C[nt], a0, a1, a2, a3, b.x, b.y);
            }
        }

        // ---- layer 1: fragment passthrough (relu + f16x2 pack), 4 K-blocks ----
        float C1[8][4];
#pragma unroll
        for (int nt = 0; nt < 8; nt++)
#pragma unroll
            for (int j = 0; j < 4; j++) C1[nt][j] = 0.0f;

#pragma unroll
        for (int kk = 0; kk < 4; kk++) {
            const uint32_t a0 = f16x2(fmaxf(C[2 * kk][0], 0.0f),     fmaxf(C[2 * kk][1], 0.0f));
            const uint32_t a1 = f16x2(fmaxf(C[2 * kk][2], 0.0f),     fmaxf(C[2 * kk][3], 0.0f));
            const uint32_t a2 = f16x2(fmaxf(C[2 * kk + 1][0], 0.0f), fmaxf(C[2 * kk + 1][1], 0.0f));
            const uint32_t a3 = f16x2(fmaxf(C[2 * kk + 1][2], 0.0f), fmaxf(C[2 * kk + 1][3], 0.0f));
#pragma unroll
            for (int nt = 0; nt < 8; nt++) {
                const uint2 b = w1f[(kk * 8 + nt) * 32 + lane];
                mma16(C1[nt], a0, a1, a2, a3, b.x, b.y);
            }
        }

        // ---- epilogue: relu + (64x3) from C1 frags, shfl reduce over t ----
        float acc[2][3] = {{0.f, 0.f, 0.f}, {0.f, 0.f, 0.f}};
#pragma unroll
        for (int nt = 0; nt < 8; nt++) {
            const int cA = nt * 8 + 2 * t;
            float2 w[3];
#pragma unroll
            for (int j = 0; j < 3; j++)
                w[j] = *reinterpret_cast<const float2*>(&w2s[j * 64 + cA]);
            const float vA0 = fmaxf(C1[nt][0], 0.0f);
            const float vB0 = fmaxf(C1[nt][1], 0.0f);
            const float vA1 = fmaxf(C1[nt][2], 0.0f);
            const float vB1 = fmaxf(C1[nt][3], 0.0f);
#pragma unroll
            for (int j = 0; j < 3; j++) {
                acc[0][j] += vA0 * w[j].x + vB0 * w[j].y;
                acc[1][j] += vA1 * w[j].x + vB1 * w[j].y;
            }
        }
#pragma unroll
        for (int r = 0; r < 2; r++)
#pragma unroll
            for (int j = 0; j < 3; j++) {
                float v = acc[r][j];
                v += __shfl_xor_sync(0xffffffffu, v, 1);
                v += __shfl_xor_sync(0xffffffffu, v, 2);
                acc[r][j] = v;
            }
        if (t == 0) {
#pragma unroll
            for (int r = 0; r < 2; r++) {
                const int pid = tb + g + 8 * r;
#pragma unroll
                for (int j = 0; j < 3; j++) out[j * NPTS + pid] = acc[r][j];
            }
        }
    }
}

}  // namespace

extern "C" void kernel_launch(void* const* d_in, const int* in_sizes, int n_in,
                              void* d_out, int out_size) {
    (void)in_sizes; (void)n_in; (void)out_size;
    const float2* xy  = (const float2*)d_in[0];
    const float2* tab = (const float2*)d_in[1];
    const float*  W0  = (const float*)d_in[2];
    const float*  W1  = (const float*)d_in[3];
    const float*  W2  = (const float*)d_in[4];
    float* out = (float*)d_out;

    ngp_mma_kernel<<<GRID, THREADS>>>(xy, tab, W0, W1, W2, out);
}